// round 1
// baseline (speedup 1.0000x reference)
#include <cuda_runtime.h>
#include <cuda_bf16.h>
#include <math.h>

// Problem constants
#define T_TOK 4096      // B*S
#define HDIM 1024
#define FDIM 512
#define NEXP 8
#define TOPK 2
#define MAXP 4096       // max tokens per expert (top-2 of 8 -> <= T)

// ---------------- device scratch (no allocation allowed) ----------------
__device__ int   g_cnt[NEXP];
__device__ int   g_off[NEXP];
__device__ int   g_tok[NEXP * MAXP];
__device__ float g_wt [NEXP * MAXP];
__device__ int   g_pair[T_TOK * TOPK];           // e*MAXP + pos per (token, k)
__device__ float g_act [T_TOK * TOPK * FDIM];    // 16 MB, expert-sorted rows
__device__ float g_dout[T_TOK * TOPK * HDIM];    // 32 MB, expert-sorted rows

// ---------------- packed f32x2 helpers (FFMA2) ----------------
__device__ __forceinline__ unsigned long long pk2(float a, float b) {
    unsigned long long r;
    asm("mov.b64 %0, {%1,%2};" : "=l"(r) : "f"(a), "f"(b));
    return r;
}
__device__ __forceinline__ void fma2(unsigned long long& d,
                                     unsigned long long a,
                                     unsigned long long b) {
    asm("fma.rn.f32x2 %0, %1, %2, %0;" : "+l"(d) : "l"(a), "l"(b));
}
__device__ __forceinline__ float2 upk2(unsigned long long v) {
    float2 f;
    asm("mov.b64 {%0,%1}, %2;" : "=f"(f.x), "=f"(f.y) : "l"(v));
    return f;
}

// ---------------- kernel 0: zero counters ----------------
__global__ void zero_cnt_kernel() {
    if (threadIdx.x < NEXP) g_cnt[threadIdx.x] = 0;
}

// ---------------- kernel 1: router (1 warp per token) ----------------
__global__ __launch_bounds__(128) void router_kernel(
    const float* __restrict__ x, const float* __restrict__ Wr)
{
    int t = blockIdx.x * 4 + (threadIdx.x >> 5);
    int lane = threadIdx.x & 31;
    const float* xr = x + (size_t)t * HDIM;

    float acc[NEXP];
#pragma unroll
    for (int e = 0; e < NEXP; e++) acc[e] = 0.0f;

    for (int h = lane; h < HDIM; h += 32) {
        float xv = xr[h];
        const float4* wr4 = (const float4*)(Wr + (size_t)h * NEXP);
        float4 w0 = wr4[0], w1 = wr4[1];
        acc[0] = fmaf(xv, w0.x, acc[0]);
        acc[1] = fmaf(xv, w0.y, acc[1]);
        acc[2] = fmaf(xv, w0.z, acc[2]);
        acc[3] = fmaf(xv, w0.w, acc[3]);
        acc[4] = fmaf(xv, w1.x, acc[4]);
        acc[5] = fmaf(xv, w1.y, acc[5]);
        acc[6] = fmaf(xv, w1.z, acc[6]);
        acc[7] = fmaf(xv, w1.w, acc[7]);
    }
#pragma unroll
    for (int e = 0; e < NEXP; e++) {
#pragma unroll
        for (int o = 16; o > 0; o >>= 1)
            acc[e] += __shfl_xor_sync(0xFFFFFFFFu, acc[e], o);
    }

    if (lane == 0) {
        float m = acc[0];
#pragma unroll
        for (int e = 1; e < NEXP; e++) m = fmaxf(m, acc[e]);
        float p[NEXP];
#pragma unroll
        for (int e = 0; e < NEXP; e++) p[e] = expf(acc[e] - m);
        // top-2 (first occurrence on ties, matching jax top_k)
        int i0 = 0;
#pragma unroll
        for (int e = 1; e < NEXP; e++) if (p[e] > p[i0]) i0 = e;
        int i1 = (i0 == 0) ? 1 : 0;
#pragma unroll
        for (int e = 0; e < NEXP; e++)
            if (e != i0 && p[e] > p[i1]) i1 = e;
        float s = p[i0] + p[i1];
        float w0 = p[i0] / s;
        float w1 = p[i1] / s;

        int p0 = atomicAdd(&g_cnt[i0], 1);
        g_tok[i0 * MAXP + p0] = t;
        g_wt [i0 * MAXP + p0] = w0;
        g_pair[t * 2 + 0] = i0 * MAXP + p0;

        int p1 = atomicAdd(&g_cnt[i1], 1);
        g_tok[i1 * MAXP + p1] = t;
        g_wt [i1 * MAXP + p1] = w1;
        g_pair[t * 2 + 1] = i1 * MAXP + p1;
    }
}

// ---------------- kernel 2: tiny exclusive scan ----------------
__global__ void scan_kernel() {
    if (threadIdx.x == 0) {
        int o = 0;
        for (int e = 0; e < NEXP; e++) { g_off[e] = o; o += g_cnt[e]; }
    }
}

// ---------------- kernel 3: gate+up GEMM + SwiGLU (expert-sorted) ----------------
// tile: 64 rows (tokens of this expert) x 64 cols (F), K-blocked by 16 over H.
__global__ __launch_bounds__(256, 2) void gemm_gateup_kernel(
    const float* __restrict__ x,
    const float* __restrict__ Wg,
    const float* __restrict__ Wu)
{
    int e = blockIdx.z;
    int cnt = g_cnt[e];
    int m0 = blockIdx.x * 64;
    if (m0 >= cnt) return;
    int f0 = blockIdx.y * 64;

    __shared__ float As [16][68];
    __shared__ float Bgs[16][68];
    __shared__ float Bus[16][68];
    __shared__ int   s_tok[64];
    __shared__ float s_w[64];

    int tid = threadIdx.x;
    if (tid < 64) {
        int r = m0 + tid;
        int tok; float w;
        if (r < cnt) { tok = g_tok[e * MAXP + r]; w = g_wt[e * MAXP + r]; }
        else         { tok = g_tok[e * MAXP];     w = 0.0f; }
        s_tok[tid] = tok;
        s_w[tid] = w;
    }
    __syncthreads();

    int tx = tid & 15, ty = tid >> 4;
    int tm = ty * 4, tn = tx * 4;

    unsigned long long accg[8], accu[8];
#pragma unroll
    for (int i = 0; i < 8; i++) { accg[i] = 0ULL; accu[i] = 0ULL; }

    // per-thread load coords
    int am = tid >> 2;             // row 0..63
    int akq = (tid & 3) * 4;       // k quad 0,4,8,12
    int bk = tid >> 4;             // 0..15
    int bn = (tid & 15) * 4;       // 0..60

    const size_t wbase = (size_t)e * HDIM * FDIM;
    const float* xrow = x + (size_t)s_tok[am] * HDIM;

    for (int kb = 0; kb < HDIM; kb += 16) {
        float4 av = *(const float4*)(xrow + kb + akq);
        As[akq + 0][am] = av.x;
        As[akq + 1][am] = av.y;
        As[akq + 2][am] = av.z;
        As[akq + 3][am] = av.w;
        *(float4*)&Bgs[bk][bn] = *(const float4*)(Wg + wbase + (size_t)(kb + bk) * FDIM + f0 + bn);
        *(float4*)&Bus[bk][bn] = *(const float4*)(Wu + wbase + (size_t)(kb + bk) * FDIM + f0 + bn);
        __syncthreads();

#pragma unroll
        for (int k = 0; k < 16; k++) {
            float4 a  = *(const float4*)&As [k][tm];
            float4 bg = *(const float4*)&Bgs[k][tn];
            float4 bu = *(const float4*)&Bus[k][tn];
            unsigned long long bg0 = pk2(bg.x, bg.y), bg1 = pk2(bg.z, bg.w);
            unsigned long long bu0 = pk2(bu.x, bu.y), bu1 = pk2(bu.z, bu.w);
            float aa[4] = {a.x, a.y, a.z, a.w};
#pragma unroll
            for (int i = 0; i < 4; i++) {
                unsigned long long ai = pk2(aa[i], aa[i]);
                fma2(accg[i * 2 + 0], ai, bg0);
                fma2(accg[i * 2 + 1], ai, bg1);
                fma2(accu[i * 2 + 0], ai, bu0);
                fma2(accu[i * 2 + 1], ai, bu1);
            }
        }
        __syncthreads();
    }

    // epilogue: act = w * silu(gate) * up
    int gbase = g_off[e];
#pragma unroll
    for (int i = 0; i < 4; i++) {
        int r = m0 + tm + i;
        if (r >= cnt) break;
        float w = s_w[tm + i];
        float2 ga = upk2(accg[i * 2 + 0]);
        float2 gb = upk2(accg[i * 2 + 1]);
        float2 ua = upk2(accu[i * 2 + 0]);
        float2 ub = upk2(accu[i * 2 + 1]);
        float4 outv;
        outv.x = w * (ga.x / (1.0f + expf(-ga.x))) * ua.x;
        outv.y = w * (ga.y / (1.0f + expf(-ga.y))) * ua.y;
        outv.z = w * (gb.x / (1.0f + expf(-gb.x))) * ub.x;
        outv.w = w * (gb.y / (1.0f + expf(-gb.y))) * ub.y;
        *(float4*)(g_act + (size_t)(gbase + r) * FDIM + f0 + tn) = outv;
    }
}

// ---------------- kernel 4: down GEMM (expert-sorted, contiguous A) ----------------
__global__ __launch_bounds__(256, 2) void gemm_down_kernel(
    const float* __restrict__ Wd)
{
    int e = blockIdx.z;
    int cnt = g_cnt[e];
    int m0 = blockIdx.x * 64;
    if (m0 >= cnt) return;
    int h0 = blockIdx.y * 64;

    __shared__ float As[16][68];
    __shared__ float Bs[16][68];

    int tid = threadIdx.x;
    int tx = tid & 15, ty = tid >> 4;
    int tm = ty * 4, tn = tx * 4;

    unsigned long long acc[8];
#pragma unroll
    for (int i = 0; i < 8; i++) acc[i] = 0ULL;

    int am = tid >> 2;
    int akq = (tid & 3) * 4;
    int bk = tid >> 4;
    int bn = (tid & 15) * 4;

    int gbase = g_off[e];
    int arow = gbase + min(m0 + am, cnt - 1);
    const float* Arow = g_act + (size_t)arow * FDIM;
    const size_t wbase = (size_t)e * FDIM * HDIM;

    for (int kb = 0; kb < FDIM; kb += 16) {
        float4 av = *(const float4*)(Arow + kb + akq);
        As[akq + 0][am] = av.x;
        As[akq + 1][am] = av.y;
        As[akq + 2][am] = av.z;
        As[akq + 3][am] = av.w;
        *(float4*)&Bs[bk][bn] = *(const float4*)(Wd + wbase + (size_t)(kb + bk) * HDIM + h0 + bn);
        __syncthreads();

#pragma unroll
        for (int k = 0; k < 16; k++) {
            float4 a = *(const float4*)&As[k][tm];
            float4 b = *(const float4*)&Bs[k][tn];
            unsigned long long b0 = pk2(b.x, b.y), b1 = pk2(b.z, b.w);
            float aa[4] = {a.x, a.y, a.z, a.w};
#pragma unroll
            for (int i = 0; i < 4; i++) {
                unsigned long long ai = pk2(aa[i], aa[i]);
                fma2(acc[i * 2 + 0], ai, b0);
                fma2(acc[i * 2 + 1], ai, b1);
            }
        }
        __syncthreads();
    }

#pragma unroll
    for (int i = 0; i < 4; i++) {
        int r = m0 + tm + i;
        if (r >= cnt) break;
        float2 a0 = upk2(acc[i * 2 + 0]);
        float2 a1 = upk2(acc[i * 2 + 1]);
        float4 outv = {a0.x, a0.y, a1.x, a1.y};
        *(float4*)(g_dout + (size_t)(gbase + r) * HDIM + h0 + tn) = outv;
    }
}

// ---------------- kernel 5: combine the two expert contributions ----------------
__global__ __launch_bounds__(256) void combine_kernel(float* __restrict__ out)
{
    int idx = blockIdx.x * blockDim.x + threadIdx.x;   // over T*H/4
    int t = idx >> 8;                                  // H/4 = 256
    int hq = (idx & 255) * 4;

    int v0 = g_pair[t * 2 + 0];
    int v1 = g_pair[t * 2 + 1];
    int gi0 = g_off[v0 >> 12] + (v0 & (MAXP - 1));
    int gi1 = g_off[v1 >> 12] + (v1 & (MAXP - 1));

    float4 a = *(const float4*)(g_dout + (size_t)gi0 * HDIM + hq);
    float4 b = *(const float4*)(g_dout + (size_t)gi1 * HDIM + hq);
    float4 o = {a.x + b.x, a.y + b.y, a.z + b.z, a.w + b.w};
    *(float4*)(out + (size_t)t * HDIM + hq) = o;
}

// ---------------- launch ----------------
extern "C" void kernel_launch(void* const* d_in, const int* in_sizes, int n_in,
                              void* d_out, int out_size)
{
    const float* x  = (const float*)d_in[0];
    const float* Wr = (const float*)d_in[1];
    const float* Wg = (const float*)d_in[2];
    const float* Wu = (const float*)d_in[3];
    const float* Wd = (const float*)d_in[4];
    float* out = (float*)d_out;

    zero_cnt_kernel<<<1, 32>>>();
    router_kernel<<<T_TOK / 4, 128>>>(x, Wr);
    scan_kernel<<<1, 32>>>();

    dim3 g2(MAXP / 64, FDIM / 64, NEXP);   // 64 x 8 x 8
    gemm_gateup_kernel<<<g2, 256>>>(x, Wg, Wu);

    dim3 g3(MAXP / 64, HDIM / 64, NEXP);   // 64 x 16 x 8
    gemm_down_kernel<<<g3, 256>>>(Wd);

    combine_kernel<<<(T_TOK * HDIM / 4) / 256, 256>>>(out);
}

// round 4
// speedup vs baseline: 1.7772x; 1.7772x over previous
#include <cuda_runtime.h>
#include <math.h>
#include <stdint.h>

#define T_TOK 4096
#define HDIM 1024
#define FDIM 512
#define NEXP 8
#define MAXP 4096

// ---------------- device scratch ----------------
__device__ int   g_cnt[NEXP];
__device__ int   g_off[NEXP];
__device__ int   g_tok[NEXP * MAXP];
__device__ float g_wt [NEXP * MAXP];
__device__ int   g_pair[T_TOK * 2];
__device__ float g_act [T_TOK * 2 * FDIM];
__device__ float g_dout[T_TOK * 2 * HDIM];

__device__ __forceinline__ uint32_t tf32r(float f) {
    uint32_t r; asm("cvt.rna.tf32.f32 %0, %1;" : "=r"(r) : "f"(f)); return r;
}

#define MMA(c, a0, a1, a2, a3, b0, b1) \
    asm volatile("mma.sync.aligned.m16n8k8.row.col.f32.tf32.tf32.f32 " \
        "{%0,%1,%2,%3},{%4,%5,%6,%7},{%8,%9},{%0,%1,%2,%3};" \
        : "+f"((c)[0]), "+f"((c)[1]), "+f"((c)[2]), "+f"((c)[3]) \
        : "r"(a0), "r"(a1), "r"(a2), "r"(a3), "r"(b0), "r"(b1))

#define KS 36   // smem row stride in words (conflict-free: (4r+k) mod 32 is a permutation)

// ---------------- tiny setup ----------------
__global__ void zero_cnt_kernel() { if (threadIdx.x < NEXP) g_cnt[threadIdx.x] = 0; }
__global__ void scan_kernel() {
    if (threadIdx.x == 0) {
        int o = 0;
        for (int e = 0; e < NEXP; e++) { g_off[e] = o; o += g_cnt[e]; }
    }
}

// ---------------- router (fp32-exact) ----------------
__global__ __launch_bounds__(128) void router_kernel(
    const float* __restrict__ x, const float* __restrict__ Wr)
{
    int t = blockIdx.x * 4 + (threadIdx.x >> 5);
    int lane = threadIdx.x & 31;
    const float* xr = x + (size_t)t * HDIM;
    float acc[NEXP];
#pragma unroll
    for (int e = 0; e < NEXP; e++) acc[e] = 0.0f;
    for (int h = lane; h < HDIM; h += 32) {
        float xv = xr[h];
        const float4* wr4 = (const float4*)(Wr + (size_t)h * NEXP);
        float4 w0 = wr4[0], w1 = wr4[1];
        acc[0] = fmaf(xv, w0.x, acc[0]); acc[1] = fmaf(xv, w0.y, acc[1]);
        acc[2] = fmaf(xv, w0.z, acc[2]); acc[3] = fmaf(xv, w0.w, acc[3]);
        acc[4] = fmaf(xv, w1.x, acc[4]); acc[5] = fmaf(xv, w1.y, acc[5]);
        acc[6] = fmaf(xv, w1.z, acc[6]); acc[7] = fmaf(xv, w1.w, acc[7]);
    }
#pragma unroll
    for (int e = 0; e < NEXP; e++)
#pragma unroll
        for (int o = 16; o > 0; o >>= 1)
            acc[e] += __shfl_xor_sync(0xFFFFFFFFu, acc[e], o);
    if (lane == 0) {
        float m = acc[0];
#pragma unroll
        for (int e = 1; e < NEXP; e++) m = fmaxf(m, acc[e]);
        float p[NEXP];
#pragma unroll
        for (int e = 0; e < NEXP; e++) p[e] = expf(acc[e] - m);
        int i0 = 0;
#pragma unroll
        for (int e = 1; e < NEXP; e++) if (p[e] > p[i0]) i0 = e;
        int i1 = (i0 == 0) ? 1 : 0;
#pragma unroll
        for (int e = 0; e < NEXP; e++) if (e != i0 && p[e] > p[i1]) i1 = e;
        float s = p[i0] + p[i1];
        int p0 = atomicAdd(&g_cnt[i0], 1);
        g_tok[i0 * MAXP + p0] = t; g_wt[i0 * MAXP + p0] = p[i0] / s;
        g_pair[t * 2 + 0] = i0 * MAXP + p0;
        int p1 = atomicAdd(&g_cnt[i1], 1);
        g_tok[i1 * MAXP + p1] = t; g_wt[i1 * MAXP + p1] = p[i1] / s;
        g_pair[t * 2 + 1] = i1 * MAXP + p1;
    }
}

// ---------------- gate+up tf32 mma.sync + SwiGLU ----------------
// Block tile M=128 tokens x N=64 (per gate AND up), BK=32, 256 threads.
// 8 warps as 4(m) x 2(n); warp tile 32x32; per warp: 2 m-tiles x 4 n-tiles, two acc sets.
// smem words/buffer: A 128*36=4608, Bg 64*36=2304, Bu 2304 -> 9216; x2 buffers; meta 256.
#define GU_SMEM ((2 * 9216 + 256) * 4)
__global__ __launch_bounds__(256, 1) void mg_gateup(
    const float* __restrict__ x,
    const float* __restrict__ Wg,
    const float* __restrict__ Wu)
{
    extern __shared__ uint32_t sm[];
    int e = blockIdx.z;
    int cnt = g_cnt[e];
    int m0 = blockIdx.x * 128;
    if (m0 >= cnt) return;
    int f0 = blockIdx.y * 64;

    int tid = threadIdx.x, lane = tid & 31, wid = tid >> 5;
    int wm = wid & 3, wn = wid >> 2;
    int lr = lane >> 2, l3 = lane & 3;

    int*   stok = (int*)(sm + 18432);
    float* swt  = (float*)(sm + 18560);
    if (tid < 128) {
        int r = m0 + tid, rc = min(r, cnt - 1);
        stok[tid] = g_tok[e * MAXP + rc];
        swt[tid]  = (r < cnt) ? g_wt[e * MAXP + rc] : 0.0f;
    }
    __syncthreads();

    const float* WgB = Wg + (size_t)e * HDIM * FDIM + f0;
    const float* WuB = Wu + (size_t)e * HDIM * FDIM + f0;

    float4 ra[4], rg[2], ru[2];

    auto LOAD = [&](int s) {
        int kb = s * 32;
#pragma unroll
        for (int i = 0; i < 4; i++) {
            int idx = i * 256 + tid, am = idx >> 3, akq = (idx & 7) * 4;
            ra[i] = *(const float4*)(x + (size_t)stok[am] * HDIM + kb + akq);
        }
#pragma unroll
        for (int i = 0; i < 2; i++) {
            int idx = i * 256 + tid, bk = idx & 31, bn = (idx >> 5) * 4;
            rg[i] = *(const float4*)(WgB + (size_t)(kb + bk) * FDIM + bn);
            ru[i] = *(const float4*)(WuB + (size_t)(kb + bk) * FDIM + bn);
        }
    };
    auto STORE = [&](int b) {
        uint32_t* A  = sm + b * 9216;
        uint32_t* Bg = A + 4608;
        uint32_t* Bu = A + 6912;
#pragma unroll
        for (int i = 0; i < 4; i++) {
            int idx = i * 256 + tid, am = idx >> 3, akq = (idx & 7) * 4;
            uint32_t* p = A + am * KS + akq;
            p[0] = tf32r(ra[i].x); p[1] = tf32r(ra[i].y);
            p[2] = tf32r(ra[i].z); p[3] = tf32r(ra[i].w);
        }
#pragma unroll
        for (int i = 0; i < 2; i++) {
            int idx = i * 256 + tid, bk = idx & 31, bn = (idx >> 5) * 4;
            Bg[(bn + 0) * KS + bk] = tf32r(rg[i].x);
            Bg[(bn + 1) * KS + bk] = tf32r(rg[i].y);
            Bg[(bn + 2) * KS + bk] = tf32r(rg[i].z);
            Bg[(bn + 3) * KS + bk] = tf32r(rg[i].w);
            Bu[(bn + 0) * KS + bk] = tf32r(ru[i].x);
            Bu[(bn + 1) * KS + bk] = tf32r(ru[i].y);
            Bu[(bn + 2) * KS + bk] = tf32r(ru[i].z);
            Bu[(bn + 3) * KS + bk] = tf32r(ru[i].w);
        }
    };

    float cg[2][4][4], cu[2][4][4];
#pragma unroll
    for (int a = 0; a < 2; a++)
#pragma unroll
        for (int b = 0; b < 4; b++)
#pragma unroll
            for (int c = 0; c < 4; c++) { cg[a][b][c] = 0.0f; cu[a][b][c] = 0.0f; }

    LOAD(0); STORE(0);
    const int NS = HDIM / 32;
    for (int s = 0; s < NS; s++) {
        __syncthreads();
        if (s + 1 < NS) LOAD(s + 1);
        uint32_t* A  = sm + (s & 1) * 9216;
        uint32_t* Bg = A + 4608;
        uint32_t* Bu = A + 6912;
#pragma unroll
        for (int kk = 0; kk < 32; kk += 8) {
            uint32_t af[2][4];
#pragma unroll
            for (int mt = 0; mt < 2; mt++) {
                int rb = (wm * 32 + mt * 16 + lr) * KS + kk + l3;
                af[mt][0] = A[rb];
                af[mt][1] = A[rb + 8 * KS];
                af[mt][2] = A[rb + 4];
                af[mt][3] = A[rb + 8 * KS + 4];
            }
#pragma unroll
            for (int nt = 0; nt < 4; nt++) {
                int nb = (wn * 32 + nt * 8 + lr) * KS + kk + l3;
                uint32_t bg0 = Bg[nb], bg1 = Bg[nb + 4];
                uint32_t bu0 = Bu[nb], bu1 = Bu[nb + 4];
#pragma unroll
                for (int mt = 0; mt < 2; mt++) {
                    MMA(cg[mt][nt], af[mt][0], af[mt][1], af[mt][2], af[mt][3], bg0, bg1);
                    MMA(cu[mt][nt], af[mt][0], af[mt][1], af[mt][2], af[mt][3], bu0, bu1);
                }
            }
        }
        if (s + 1 < NS) STORE((s + 1) & 1);
    }

    // epilogue: w * silu(gate) * up
    int gbase = g_off[e];
#pragma unroll
    for (int mt = 0; mt < 2; mt++)
#pragma unroll
        for (int rr = 0; rr < 2; rr++) {
            int row = wm * 32 + mt * 16 + lr + rr * 8;
            if (m0 + row < cnt) {
                float w = swt[row];
                float* dst = g_act + (size_t)(gbase + m0 + row) * FDIM + f0;
#pragma unroll
                for (int nt = 0; nt < 4; nt++) {
                    float gv0 = cg[mt][nt][rr * 2], gv1 = cg[mt][nt][rr * 2 + 1];
                    float uv0 = cu[mt][nt][rr * 2], uv1 = cu[mt][nt][rr * 2 + 1];
                    float2 o;
                    o.x = w * (gv0 / (1.0f + expf(-gv0))) * uv0;
                    o.y = w * (gv1 / (1.0f + expf(-gv1))) * uv1;
                    *(float2*)(dst + wn * 32 + nt * 8 + 2 * l3) = o;
                }
            }
        }
}

// ---------------- down tf32 mma.sync GEMM ----------------
// Block tile M=128 x N=128, BK=32, 256 threads. 8 warps as 2(m) x 4(n); warp tile 64x32.
// smem words/buffer: A 4608 + B 128*36=4608 -> 9216; x2.
#define DN_SMEM ((2 * 9216) * 4)
__global__ __launch_bounds__(256, 1) void mg_down(const float* __restrict__ Wd)
{
    extern __shared__ uint32_t sm[];
    int e = blockIdx.z;
    int cnt = g_cnt[e];
    int m0 = blockIdx.x * 128;
    if (m0 >= cnt) return;
    int h0 = blockIdx.y * 128;

    int tid = threadIdx.x, lane = tid & 31, wid = tid >> 5;
    int wm = wid & 1, wn = wid >> 1;
    int lr = lane >> 2, l3 = lane & 3;

    int gbase = g_off[e];
    const float* WdB = Wd + (size_t)e * FDIM * HDIM + h0;

    float4 ra[4], rb[4];

    auto LOAD = [&](int s) {
        int kb = s * 32;
#pragma unroll
        for (int i = 0; i < 4; i++) {
            int idx = i * 256 + tid, am = idx >> 3, akq = (idx & 7) * 4;
            int arow = gbase + min(m0 + am, cnt - 1);
            ra[i] = *(const float4*)(g_act + (size_t)arow * FDIM + kb + akq);
        }
#pragma unroll
        for (int i = 0; i < 4; i++) {
            int idx = i * 256 + tid, bk = idx & 31, bn = (idx >> 5) * 4;
            rb[i] = *(const float4*)(WdB + (size_t)(kb + bk) * HDIM + bn);
        }
    };
    auto STORE = [&](int b) {
        uint32_t* A = sm + b * 9216;
        uint32_t* B = A + 4608;
#pragma unroll
        for (int i = 0; i < 4; i++) {
            int idx = i * 256 + tid, am = idx >> 3, akq = (idx & 7) * 4;
            uint32_t* p = A + am * KS + akq;
            p[0] = tf32r(ra[i].x); p[1] = tf32r(ra[i].y);
            p[2] = tf32r(ra[i].z); p[3] = tf32r(ra[i].w);
        }
#pragma unroll
        for (int i = 0; i < 4; i++) {
            int idx = i * 256 + tid, bk = idx & 31, bn = (idx >> 5) * 4;
            B[(bn + 0) * KS + bk] = tf32r(rb[i].x);
            B[(bn + 1) * KS + bk] = tf32r(rb[i].y);
            B[(bn + 2) * KS + bk] = tf32r(rb[i].z);
            B[(bn + 3) * KS + bk] = tf32r(rb[i].w);
        }
    };

    float c[4][4][4];
#pragma unroll
    for (int a = 0; a < 4; a++)
#pragma unroll
        for (int b = 0; b < 4; b++)
#pragma unroll
            for (int k = 0; k < 4; k++) c[a][b][k] = 0.0f;

    LOAD(0); STORE(0);
    const int NS = FDIM / 32;
    for (int s = 0; s < NS; s++) {
        __syncthreads();
        if (s + 1 < NS) LOAD(s + 1);
        uint32_t* A = sm + (s & 1) * 9216;
        uint32_t* B = A + 4608;
#pragma unroll
        for (int kk = 0; kk < 32; kk += 8) {
            uint32_t af[4][4];
#pragma unroll
            for (int mt = 0; mt < 4; mt++) {
                int rb_ = (wm * 64 + mt * 16 + lr) * KS + kk + l3;
                af[mt][0] = A[rb_];
                af[mt][1] = A[rb_ + 8 * KS];
                af[mt][2] = A[rb_ + 4];
                af[mt][3] = A[rb_ + 8 * KS + 4];
            }
#pragma unroll
            for (int nt = 0; nt < 4; nt++) {
                int nb = (wn * 32 + nt * 8 + lr) * KS + kk + l3;
                uint32_t b0 = B[nb], b1 = B[nb + 4];
#pragma unroll
                for (int mt = 0; mt < 4; mt++)
                    MMA(c[mt][nt], af[mt][0], af[mt][1], af[mt][2], af[mt][3], b0, b1);
            }
        }
        if (s + 1 < NS) STORE((s + 1) & 1);
    }

#pragma unroll
    for (int mt = 0; mt < 4; mt++)
#pragma unroll
        for (int rr = 0; rr < 2; rr++) {
            int row = wm * 64 + mt * 16 + lr + rr * 8;
            if (m0 + row < cnt) {
                float* dst = g_dout + (size_t)(gbase + m0 + row) * HDIM + h0;
#pragma unroll
                for (int nt = 0; nt < 4; nt++) {
                    float2 o = { c[mt][nt][rr * 2], c[mt][nt][rr * 2 + 1] };
                    *(float2*)(dst + wn * 32 + nt * 8 + 2 * l3) = o;
                }
            }
        }
}

// ---------------- combine ----------------
__global__ __launch_bounds__(256) void combine_kernel(float* __restrict__ out)
{
    int idx = blockIdx.x * blockDim.x + threadIdx.x;
    int t = idx >> 8;
    int hq = (idx & 255) * 4;
    int v0 = g_pair[t * 2 + 0], v1 = g_pair[t * 2 + 1];
    int gi0 = g_off[v0 >> 12] + (v0 & (MAXP - 1));
    int gi1 = g_off[v1 >> 12] + (v1 & (MAXP - 1));
    float4 a = *(const float4*)(g_dout + (size_t)gi0 * HDIM + hq);
    float4 b = *(const float4*)(g_dout + (size_t)gi1 * HDIM + hq);
    float4 o = {a.x + b.x, a.y + b.y, a.z + b.z, a.w + b.w};
    *(float4*)(out + (size_t)t * HDIM + hq) = o;
}

// ---------------- launch ----------------
extern "C" void kernel_launch(void* const* d_in, const int* in_sizes, int n_in,
                              void* d_out, int out_size)
{
    const float* x  = (const float*)d_in[0];
    const float* Wr = (const float*)d_in[1];
    const float* Wg = (const float*)d_in[2];
    const float* Wu = (const float*)d_in[3];
    const float* Wd = (const float*)d_in[4];
    float* out = (float*)d_out;

    cudaFuncSetAttribute(mg_gateup, cudaFuncAttributeMaxDynamicSharedMemorySize, GU_SMEM);
    cudaFuncSetAttribute(mg_down,   cudaFuncAttributeMaxDynamicSharedMemorySize, DN_SMEM);

    zero_cnt_kernel<<<1, 32>>>();
    router_kernel<<<T_TOK / 4, 128>>>(x, Wr);
    scan_kernel<<<1, 32>>>();

    dim3 gg(MAXP / 128, FDIM / 64, NEXP);    // 32 x 8 x 8, early exit on m
    mg_gateup<<<gg, 256, GU_SMEM>>>(x, Wg, Wu);

    dim3 gd(MAXP / 128, HDIM / 128, NEXP);   // 32 x 8 x 8
    mg_down<<<gd, 256, DN_SMEM>>>(Wd);

    combine_kernel<<<(T_TOK * HDIM / 4) / 256, 256>>>(out);
}

// round 5
// speedup vs baseline: 1.8690x; 1.0517x over previous
#include <cuda_runtime.h>
#include <math.h>
#include <stdint.h>

#define T_TOK 4096
#define HDIM 1024
#define FDIM 512
#define NEXP 8
#define MAXP 4096
#define SROW 40   // smem words per row (32 data + 8 pad) — conflict-free LDS.64

// ---------------- device scratch ----------------
__device__ int   g_cnt[NEXP];
__device__ int   g_off[NEXP];
__device__ int   g_tok[NEXP * MAXP];
__device__ float g_wt [NEXP * MAXP];
__device__ int   g_pair[T_TOK * 2];
__device__ float g_act [T_TOK * 2 * FDIM];
__device__ float g_dout[T_TOK * 2 * HDIM];

__device__ __forceinline__ uint32_t tf32r(float f) {
    uint32_t r; asm("cvt.rna.tf32.f32 %0, %1;" : "=r"(r) : "f"(f)); return r;
}
#define MMA(c, a0, a1, a2, a3, b0, b1) \
    asm volatile("mma.sync.aligned.m16n8k8.row.col.f32.tf32.tf32.f32 " \
        "{%0,%1,%2,%3},{%4,%5,%6,%7},{%8,%9},{%0,%1,%2,%3};" \
        : "+f"((c)[0]), "+f"((c)[1]), "+f"((c)[2]), "+f"((c)[3]) \
        : "r"(a0), "r"(a1), "r"(a2), "r"(a3), "r"(b0), "r"(b1))

// ---------------- tiny setup ----------------
__global__ void zero_cnt_kernel() { if (threadIdx.x < NEXP) g_cnt[threadIdx.x] = 0; }
__global__ void scan_kernel() {
    if (threadIdx.x == 0) {
        int o = 0;
        for (int e = 0; e < NEXP; e++) { g_off[e] = o; o += g_cnt[e]; }
    }
}

// ---------------- router (fp32-exact) ----------------
__global__ __launch_bounds__(128) void router_kernel(
    const float* __restrict__ x, const float* __restrict__ Wr)
{
    int t = blockIdx.x * 4 + (threadIdx.x >> 5);
    int lane = threadIdx.x & 31;
    const float* xr = x + (size_t)t * HDIM;
    float acc[NEXP];
#pragma unroll
    for (int e = 0; e < NEXP; e++) acc[e] = 0.0f;
    for (int h = lane; h < HDIM; h += 32) {
        float xv = xr[h];
        const float4* wr4 = (const float4*)(Wr + (size_t)h * NEXP);
        float4 w0 = wr4[0], w1 = wr4[1];
        acc[0] = fmaf(xv, w0.x, acc[0]); acc[1] = fmaf(xv, w0.y, acc[1]);
        acc[2] = fmaf(xv, w0.z, acc[2]); acc[3] = fmaf(xv, w0.w, acc[3]);
        acc[4] = fmaf(xv, w1.x, acc[4]); acc[5] = fmaf(xv, w1.y, acc[5]);
        acc[6] = fmaf(xv, w1.z, acc[6]); acc[7] = fmaf(xv, w1.w, acc[7]);
    }
#pragma unroll
    for (int e = 0; e < NEXP; e++)
#pragma unroll
        for (int o = 16; o > 0; o >>= 1)
            acc[e] += __shfl_xor_sync(0xFFFFFFFFu, acc[e], o);
    if (lane == 0) {
        float m = acc[0];
#pragma unroll
        for (int e = 1; e < NEXP; e++) m = fmaxf(m, acc[e]);
        float p[NEXP];
#pragma unroll
        for (int e = 0; e < NEXP; e++) p[e] = expf(acc[e] - m);
        int i0 = 0;
#pragma unroll
        for (int e = 1; e < NEXP; e++) if (p[e] > p[i0]) i0 = e;
        int i1 = (i0 == 0) ? 1 : 0;
#pragma unroll
        for (int e = 0; e < NEXP; e++) if (e != i0 && p[e] > p[i1]) i1 = e;
        float s = p[i0] + p[i1];
        int p0 = atomicAdd(&g_cnt[i0], 1);
        g_tok[i0 * MAXP + p0] = t; g_wt[i0 * MAXP + p0] = p[i0] / s;
        g_pair[t * 2 + 0] = i0 * MAXP + p0;
        int p1 = atomicAdd(&g_cnt[i1], 1);
        g_tok[i1 * MAXP + p1] = t; g_wt[i1 * MAXP + p1] = p[i1] / s;
        g_pair[t * 2 + 1] = i1 * MAXP + p1;
    }
}

// =====================================================================
// gate+up GEMM + SwiGLU.  M=128 tokens x N'=256 (n' = 2*f_local + {g,u}),
// BK=32, 512 threads (16 warps as 4m x 4n), warp tile 32 x 64.
// smem buffer: A 128*40 + B 256*40 = 15360 words, double buffered.
// k packing within a row: word(k) = (k>>3)*8 + (k&3)*2 + ((k>>2)&1)
// so fragment pairs (k, k+4) are one LDS.64.
// =====================================================================
#define GU_SMEM ((2 * 15360 + 256) * 4)
__global__ __launch_bounds__(512, 1) void mg_gateup(
    const float* __restrict__ x,
    const float* __restrict__ Wg,
    const float* __restrict__ Wu)
{
    extern __shared__ uint32_t sm[];
    int e = blockIdx.z;
    int cnt = g_cnt[e];
    int m0 = blockIdx.x * 128;
    if (m0 >= cnt) return;
    int f0 = blockIdx.y * 128;

    int tid = threadIdx.x, lane = tid & 31, wid = tid >> 5;
    int wmi = wid & 3, wni = wid >> 2;
    int lr = lane >> 2, l3 = lane & 3;

    int*   stok = (int*)(sm + 30720);
    float* swt  = (float*)(sm + 30848);
    if (tid < 128) {
        int r = m0 + tid, rc = min(r, cnt - 1);
        stok[tid] = g_tok[e * MAXP + rc];
        swt[tid]  = (r < cnt) ? g_wt[e * MAXP + rc] : 0.0f;
    }
    __syncthreads();

    // staging coords
    int am = tid >> 2, ko = (tid & 3) * 8;
    const float* arow = x + (size_t)stok[am] * HDIM + ko;
    int bk = tid & 31;
    int bwrd = (bk >> 3) * 8 + (bk & 3) * 2 + ((bk >> 2) & 1);
    int fb = (tid >> 5) * 8;           // f_local base, 0..120
    const float* gp0 = Wg + (size_t)e * HDIM * FDIM + (size_t)bk * FDIM + f0 + fb;
    const float* up0 = Wu + (size_t)e * HDIM * FDIM + (size_t)bk * FDIM + f0 + fb;

    float4 ra0, ra1, vg0, vg1, vu0, vu1;
    auto LOAD = [&](int s) {
        int kb = s * 32;
        ra0 = *(const float4*)(arow + kb);
        ra1 = *(const float4*)(arow + kb + 4);
        const float* gp = gp0 + (size_t)kb * FDIM;
        const float* up = up0 + (size_t)kb * FDIM;
        vg0 = *(const float4*)gp;       vg1 = *(const float4*)(gp + 4);
        vu0 = *(const float4*)up;       vu1 = *(const float4*)(up + 4);
    };
    auto STORE = [&](int b) {
        uint32_t* A = sm + b * 15360;
        uint32_t* B = A + 5120;
        uint2* pa = (uint2*)(A + am * SROW + ko);
        pa[0] = make_uint2(tf32r(ra0.x), tf32r(ra1.x));
        pa[1] = make_uint2(tf32r(ra0.y), tf32r(ra1.y));
        pa[2] = make_uint2(tf32r(ra0.z), tf32r(ra1.z));
        pa[3] = make_uint2(tf32r(ra0.w), tf32r(ra1.w));
        uint32_t* pb = B + bwrd;
        const float* g4[2] = {(const float*)&vg0, (const float*)&vg1};
        const float* u4[2] = {(const float*)&vu0, (const float*)&vu1};
#pragma unroll
        for (int jj = 0; jj < 2; jj++)
#pragma unroll
            for (int i = 0; i < 4; i++) {
                int fl = fb + jj * 4 + i;
                pb[(2 * fl + 0) * SROW] = tf32r(g4[jj][i]);
                pb[(2 * fl + 1) * SROW] = tf32r(u4[jj][i]);
            }
    };

    float c[2][8][4];
#pragma unroll
    for (int a = 0; a < 2; a++)
#pragma unroll
        for (int b = 0; b < 8; b++)
#pragma unroll
            for (int k = 0; k < 4; k++) c[a][b][k] = 0.0f;

    LOAD(0); STORE(0);
    const int NS = HDIM / 32;
    for (int s = 0; s < NS; s++) {
        __syncthreads();
        if (s + 1 < NS) LOAD(s + 1);
        uint32_t* A = sm + (s & 1) * 15360;
        uint32_t* B = A + 5120;
#pragma unroll
        for (int kk = 0; kk < 32; kk += 8) {
            int co = kk + l3 * 2;
            uint2 p0  = *(uint2*)(A + (wmi * 32 + lr) * SROW + co);
            uint2 p0h = *(uint2*)(A + (wmi * 32 + lr + 8) * SROW + co);
            uint2 p1  = *(uint2*)(A + (wmi * 32 + 16 + lr) * SROW + co);
            uint2 p1h = *(uint2*)(A + (wmi * 32 + 24 + lr) * SROW + co);
#pragma unroll
            for (int nt = 0; nt < 8; nt++) {
                uint2 b = *(uint2*)(B + (wni * 64 + nt * 8 + lr) * SROW + co);
                MMA(c[0][nt], p0.x, p0h.x, p0.y, p0h.y, b.x, b.y);
                MMA(c[1][nt], p1.x, p1h.x, p1.y, p1h.y, b.x, b.y);
            }
        }
        if (s + 1 < NS) STORE((s + 1) & 1);
    }

    // epilogue: c[..][rr*2] = gate, c[..][rr*2+1] = up for f = wni*32 + nt*4 + l3
    int gbase = g_off[e];
#pragma unroll
    for (int mt = 0; mt < 2; mt++)
#pragma unroll
        for (int rr = 0; rr < 2; rr++) {
            int row = wmi * 32 + mt * 16 + lr + rr * 8;
            if (m0 + row < cnt) {
                float w = swt[row];
                float* dst = g_act + (size_t)(gbase + m0 + row) * FDIM + f0 + wni * 32;
#pragma unroll
                for (int nt = 0; nt < 8; nt++) {
                    float gv = c[mt][nt][rr * 2], uv = c[mt][nt][rr * 2 + 1];
                    dst[nt * 4 + l3] = w * (gv / (1.0f + expf(-gv))) * uv;
                }
            }
        }
}

// =====================================================================
// down GEMM. M=128 rows x N=256 H-cols, BK=32, 512 threads, warp 32x64.
// =====================================================================
#define DN_SMEM ((2 * 15360) * 4)
__global__ __launch_bounds__(512, 1) void mg_down(const float* __restrict__ Wd)
{
    extern __shared__ uint32_t sm[];
    int e = blockIdx.z;
    int cnt = g_cnt[e];
    int m0 = blockIdx.x * 128;
    if (m0 >= cnt) return;
    int h0 = blockIdx.y * 256;

    int tid = threadIdx.x, lane = tid & 31, wid = tid >> 5;
    int wmi = wid & 3, wni = wid >> 2;
    int lr = lane >> 2, l3 = lane & 3;
    int gbase = g_off[e];

    int am = tid >> 2, ko = (tid & 3) * 8;
    const float* arow = g_act + (size_t)(gbase + min(m0 + am, cnt - 1)) * FDIM + ko;
    int bk = tid & 31;
    int bwrd = (bk >> 3) * 8 + (bk & 3) * 2 + ((bk >> 2) & 1);
    int nb = (tid >> 5) * 16;          // n base 0..240
    const float* dp0 = Wd + (size_t)e * FDIM * HDIM + (size_t)bk * HDIM + h0 + nb;

    float4 ra0, ra1, rb0, rb1, rb2, rb3;
    auto LOAD = [&](int s) {
        int kb = s * 32;
        ra0 = *(const float4*)(arow + kb);
        ra1 = *(const float4*)(arow + kb + 4);
        const float* dp = dp0 + (size_t)kb * HDIM;
        rb0 = *(const float4*)dp;        rb1 = *(const float4*)(dp + 4);
        rb2 = *(const float4*)(dp + 8);  rb3 = *(const float4*)(dp + 12);
    };
    auto STORE = [&](int b) {
        uint32_t* A = sm + b * 15360;
        uint32_t* B = A + 5120;
        uint2* pa = (uint2*)(A + am * SROW + ko);
        pa[0] = make_uint2(tf32r(ra0.x), tf32r(ra1.x));
        pa[1] = make_uint2(tf32r(ra0.y), tf32r(ra1.y));
        pa[2] = make_uint2(tf32r(ra0.z), tf32r(ra1.z));
        pa[3] = make_uint2(tf32r(ra0.w), tf32r(ra1.w));
        uint32_t* pb = B + bwrd;
        const float* b4[4] = {(const float*)&rb0, (const float*)&rb1,
                              (const float*)&rb2, (const float*)&rb3};
#pragma unroll
        for (int jj = 0; jj < 4; jj++)
#pragma unroll
            for (int i = 0; i < 4; i++)
                pb[(nb + jj * 4 + i) * SROW] = tf32r(b4[jj][i]);
    };

    float c[2][8][4];
#pragma unroll
    for (int a = 0; a < 2; a++)
#pragma unroll
        for (int b = 0; b < 8; b++)
#pragma unroll
            for (int k = 0; k < 4; k++) c[a][b][k] = 0.0f;

    LOAD(0); STORE(0);
    const int NS = FDIM / 32;
    for (int s = 0; s < NS; s++) {
        __syncthreads();
        if (s + 1 < NS) LOAD(s + 1);
        uint32_t* A = sm + (s & 1) * 15360;
        uint32_t* B = A + 5120;
#pragma unroll
        for (int kk = 0; kk < 32; kk += 8) {
            int co = kk + l3 * 2;
            uint2 p0  = *(uint2*)(A + (wmi * 32 + lr) * SROW + co);
            uint2 p0h = *(uint2*)(A + (wmi * 32 + lr + 8) * SROW + co);
            uint2 p1  = *(uint2*)(A + (wmi * 32 + 16 + lr) * SROW + co);
            uint2 p1h = *(uint2*)(A + (wmi * 32 + 24 + lr) * SROW + co);
#pragma unroll
            for (int nt = 0; nt < 8; nt++) {
                uint2 b = *(uint2*)(B + (wni * 64 + nt * 8 + lr) * SROW + co);
                MMA(c[0][nt], p0.x, p0h.x, p0.y, p0h.y, b.x, b.y);
                MMA(c[1][nt], p1.x, p1h.x, p1.y, p1h.y, b.x, b.y);
            }
        }
        if (s + 1 < NS) STORE((s + 1) & 1);
    }

#pragma unroll
    for (int mt = 0; mt < 2; mt++)
#pragma unroll
        for (int rr = 0; rr < 2; rr++) {
            int row = wmi * 32 + mt * 16 + lr + rr * 8;
            if (m0 + row < cnt) {
                float* dst = g_dout + (size_t)(gbase + m0 + row) * HDIM + h0 + wni * 64;
#pragma unroll
                for (int nt = 0; nt < 8; nt++)
                    *(float2*)(dst + nt * 8 + 2 * l3) =
                        make_float2(c[mt][nt][rr * 2], c[mt][nt][rr * 2 + 1]);
            }
        }
}

// ---------------- combine ----------------
__global__ __launch_bounds__(256) void combine_kernel(float* __restrict__ out)
{
    int idx = blockIdx.x * blockDim.x + threadIdx.x;
    int t = idx >> 8;
    int hq = (idx & 255) * 4;
    int v0 = g_pair[t * 2 + 0], v1 = g_pair[t * 2 + 1];
    int gi0 = g_off[v0 >> 12] + (v0 & (MAXP - 1));
    int gi1 = g_off[v1 >> 12] + (v1 & (MAXP - 1));
    float4 a = *(const float4*)(g_dout + (size_t)gi0 * HDIM + hq);
    float4 b = *(const float4*)(g_dout + (size_t)gi1 * HDIM + hq);
    float4 o = {a.x + b.x, a.y + b.y, a.z + b.z, a.w + b.w};
    *(float4*)(out + (size_t)t * HDIM + hq) = o;
}

// ---------------- launch ----------------
extern "C" void kernel_launch(void* const* d_in, const int* in_sizes, int n_in,
                              void* d_out, int out_size)
{
    const float* x  = (const float*)d_in[0];
    const float* Wr = (const float*)d_in[1];
    const float* Wg = (const float*)d_in[2];
    const float* Wu = (const float*)d_in[3];
    const float* Wd = (const float*)d_in[4];
    float* out = (float*)d_out;

    cudaFuncSetAttribute(mg_gateup, cudaFuncAttributeMaxDynamicSharedMemorySize, GU_SMEM);
    cudaFuncSetAttribute(mg_down,   cudaFuncAttributeMaxDynamicSharedMemorySize, DN_SMEM);

    zero_cnt_kernel<<<1, 32>>>();
    router_kernel<<<T_TOK / 4, 128>>>(x, Wr);
    scan_kernel<<<1, 32>>>();

    dim3 gg(MAXP / 128, FDIM / 128, NEXP);   // 32 x 4 x 8, early-exit on m
    mg_gateup<<<gg, 512, GU_SMEM>>>(x, Wg, Wu);

    dim3 gd(MAXP / 128, HDIM / 256, NEXP);   // 32 x 4 x 8
    mg_down<<<gd, 512, DN_SMEM>>>(Wd);

    combine_kernel<<<(T_TOK * HDIM / 4) / 256, 256>>>(out);
}

// round 6
// speedup vs baseline: 2.5534x; 1.3661x over previous
#include <cuda_runtime.h>
#include <math.h>
#include <stdint.h>

#define T_TOK 4096
#define HDIM 1024
#define FDIM 512
#define NEXP 8
#define MAXP 4096

// ---------------- device scratch ----------------
__device__ int   g_cnt[NEXP];
__device__ int   g_off[NEXP];
__device__ int   g_tok[NEXP * MAXP];
__device__ float g_wt [NEXP * MAXP];
__device__ int   g_pair[T_TOK * 2];
__device__ float g_act [T_TOK * 2 * FDIM];
__device__ float g_dout[T_TOK * 2 * HDIM];

__device__ __forceinline__ uint32_t tf32r(float f) {
    uint32_t r; asm("cvt.rna.tf32.f32 %0, %1;" : "=r"(r) : "f"(f)); return r;
}
#define MMA(c, a0, a1, a2, a3, b0, b1) \
    asm volatile("mma.sync.aligned.m16n8k8.row.col.f32.tf32.tf32.f32 " \
        "{%0,%1,%2,%3},{%4,%5,%6,%7},{%8,%9},{%0,%1,%2,%3};" \
        : "+f"((c)[0]), "+f"((c)[1]), "+f"((c)[2]), "+f"((c)[3]) \
        : "r"(a0), "r"(a1), "r"(a2), "r"(a3), "r"(b0), "r"(b1))

// smem geometry (words). A: k-major 16 x 136 (128 m + pad). B: k-major 16 x 264 (256 n' + pad).
#define AST 136
#define BST 264
#define BUFW (16 * AST + 16 * BST)     // 6400 words per buffer
#define ABUF(b) ((b) * BUFW)
#define BBUF(b) ((b) * BUFW + 16 * AST)
#define METAW   (2 * BUFW)
#define GEMM_SMEM ((2 * BUFW + 320) * 4)

// ---------------- tiny setup ----------------
__global__ void zero_cnt_kernel() { if (threadIdx.x < NEXP) g_cnt[threadIdx.x] = 0; }
__global__ void scan_kernel() {
    if (threadIdx.x == 0) {
        int o = 0;
        for (int e = 0; e < NEXP; e++) { g_off[e] = o; o += g_cnt[e]; }
    }
}

// ---------------- router (fp32-exact) ----------------
__global__ __launch_bounds__(128) void router_kernel(
    const float* __restrict__ x, const float* __restrict__ Wr)
{
    int t = blockIdx.x * 4 + (threadIdx.x >> 5);
    int lane = threadIdx.x & 31;
    const float* xr = x + (size_t)t * HDIM;
    float acc[NEXP];
#pragma unroll
    for (int e = 0; e < NEXP; e++) acc[e] = 0.0f;
    for (int h = lane; h < HDIM; h += 32) {
        float xv = xr[h];
        const float4* wr4 = (const float4*)(Wr + (size_t)h * NEXP);
        float4 w0 = wr4[0], w1 = wr4[1];
        acc[0] = fmaf(xv, w0.x, acc[0]); acc[1] = fmaf(xv, w0.y, acc[1]);
        acc[2] = fmaf(xv, w0.z, acc[2]); acc[3] = fmaf(xv, w0.w, acc[3]);
        acc[4] = fmaf(xv, w1.x, acc[4]); acc[5] = fmaf(xv, w1.y, acc[5]);
        acc[6] = fmaf(xv, w1.z, acc[6]); acc[7] = fmaf(xv, w1.w, acc[7]);
    }
#pragma unroll
    for (int e = 0; e < NEXP; e++)
#pragma unroll
        for (int o = 16; o > 0; o >>= 1)
            acc[e] += __shfl_xor_sync(0xFFFFFFFFu, acc[e], o);
    if (lane == 0) {
        float m = acc[0];
#pragma unroll
        for (int e = 1; e < NEXP; e++) m = fmaxf(m, acc[e]);
        float p[NEXP];
#pragma unroll
        for (int e = 0; e < NEXP; e++) p[e] = expf(acc[e] - m);
        int i0 = 0;
#pragma unroll
        for (int e = 1; e < NEXP; e++) if (p[e] > p[i0]) i0 = e;
        int i1 = (i0 == 0) ? 1 : 0;
#pragma unroll
        for (int e = 0; e < NEXP; e++) if (e != i0 && p[e] > p[i1]) i1 = e;
        float s = p[i0] + p[i1];
        int p0 = atomicAdd(&g_cnt[i0], 1);
        g_tok[i0 * MAXP + p0] = t; g_wt[i0 * MAXP + p0] = p[i0] / s;
        g_pair[t * 2 + 0] = i0 * MAXP + p0;
        int p1 = atomicAdd(&g_cnt[i1], 1);
        g_tok[i1 * MAXP + p1] = t; g_wt[i1 * MAXP + p1] = p[i1] / s;
        g_pair[t * 2 + 1] = i1 * MAXP + p1;
    }
}

// =====================================================================
// gate+up GEMM + SwiGLU. Block 128m x 256n' (n' = [gate f | 128 + up f]),
// BK=16, 256 threads, 8 warps (2m x 4n), warp tile 64x64.
// =====================================================================
__global__ __launch_bounds__(256, 1) void mg_gateup(
    const float* __restrict__ x,
    const float* __restrict__ Wg,
    const float* __restrict__ Wu)
{
    extern __shared__ uint32_t sm[];
    int e = blockIdx.z;
    int cnt = g_cnt[e];
    int m0 = blockIdx.x * 128;
    if (m0 >= cnt) return;
    int f0 = blockIdx.y * 128;

    int tid = threadIdx.x, lane = tid & 31, wid = tid >> 5;
    int wmi = wid >> 2, wni = wid & 3;
    int lr = lane >> 2, l3 = lane & 3;

    int*   stok = (int*)(sm + METAW);
    float* swt  = (float*)(sm + METAW + 128);
    {
        int r = m0 + (tid & 127), rc = min(r, cnt - 1);
        if (tid < 128) { stok[tid] = g_tok[e * MAXP + rc];
                         swt[tid]  = (r < cnt) ? g_wt[e * MAXP + rc] : 0.0f; }
    }
    __syncthreads();

    // A staging: am = tid>>1 row, kb8 = (tid&1)*8 -> 8 consecutive k
    int am = tid >> 1, kb8 = (tid & 1) * 8;
    const float* arow = x + (size_t)stok[am] * HDIM + kb8;
    // B staging: fq = (tid&31)*4 cols, kq = tid>>5 (k and k+8)
    int fq = (lane) * 4, kq = wid;
    const float* gB = Wg + (size_t)e * HDIM * FDIM + (size_t)kq * FDIM + f0 + fq;
    const float* uB = Wu + (size_t)e * HDIM * FDIM + (size_t)kq * FDIM + f0 + fq;
    uint32_t bswz = 4 * (kq & 1);    // column swizzle for this thread's k rows

    float4 ra0, ra1, vg0, vg1, vu0, vu1;
    auto LOADG = [&](int s) {
        int kb = s * 16;
        ra0 = *(const float4*)(arow + kb);
        ra1 = *(const float4*)(arow + kb + 4);
        vg0 = *(const float4*)(gB + (size_t)kb * FDIM);
        vg1 = *(const float4*)(gB + (size_t)(kb + 8) * FDIM);
        vu0 = *(const float4*)(uB + (size_t)kb * FDIM);
        vu1 = *(const float4*)(uB + (size_t)(kb + 8) * FDIM);
    };
    auto STORES = [&](int b) {
        uint32_t* A = sm + ABUF(b);
        uint32_t* B = sm + BBUF(b);
        const float* a0 = (const float*)&ra0;
        const float* a1 = (const float*)&ra1;
#pragma unroll
        for (int j = 0; j < 4; j++) {
            A[(kb8 + j) * AST + am]     = tf32r(a0[j]);
            A[(kb8 + 4 + j) * AST + am] = tf32r(a1[j]);
        }
        uint32_t cg = fq ^ bswz;
        uint4 t0 = { tf32r(vg0.x), tf32r(vg0.y), tf32r(vg0.z), tf32r(vg0.w) };
        uint4 t1 = { tf32r(vg1.x), tf32r(vg1.y), tf32r(vg1.z), tf32r(vg1.w) };
        uint4 t2 = { tf32r(vu0.x), tf32r(vu0.y), tf32r(vu0.z), tf32r(vu0.w) };
        uint4 t3 = { tf32r(vu1.x), tf32r(vu1.y), tf32r(vu1.z), tf32r(vu1.w) };
        *(uint4*)(B + kq * BST + cg)             = t0;
        *(uint4*)(B + (kq + 8) * BST + cg)       = t1;
        *(uint4*)(B + kq * BST + 128 + cg)       = t2;
        *(uint4*)(B + (kq + 8) * BST + 128 + cg) = t3;
    };

    float c[4][8][4];
#pragma unroll
    for (int a = 0; a < 4; a++)
#pragma unroll
        for (int b = 0; b < 8; b++)
#pragma unroll
            for (int k = 0; k < 4; k++) c[a][b][k] = 0.0f;

    // fragment base offsets
    int fswz = 4 * (l3 & 1);
    uint32_t aoff = l3 * AST + wmi * 64 + lr;            // + mt*16, + kk*AST
    uint32_t boff = l3 * BST + ((wni * 32 + lr) ^ fswz); // + nt*8 (+128 up), + kk*BST

    LOADG(0); STORES(0);
    const int NS = HDIM / 16;
    for (int s = 0; s < NS; s++) {
        __syncthreads();
        if (s + 1 < NS) LOADG(s + 1);
        uint32_t* A = sm + ABUF(s & 1);
        uint32_t* B = sm + BBUF(s & 1);
#pragma unroll
        for (int kk = 0; kk < 16; kk += 8) {
            uint32_t af[4][4];
#pragma unroll
            for (int mt = 0; mt < 4; mt++) {
                uint32_t w = aoff + kk * AST + mt * 16;
                af[mt][0] = A[w];
                af[mt][1] = A[w + 8];
                af[mt][2] = A[w + 4 * AST];
                af[mt][3] = A[w + 4 * AST + 8];
            }
#pragma unroll
            for (int nt = 0; nt < 8; nt++) {
                uint32_t w = boff + kk * BST + (nt & 3) * 8 + ((nt >> 2) << 7);
                uint32_t b0 = B[w], b1 = B[w + 4 * BST];
#pragma unroll
                for (int mt = 0; mt < 4; mt++)
                    MMA(c[mt][nt], af[mt][0], af[mt][1], af[mt][2], af[mt][3], b0, b1);
            }
        }
        if (s + 1 < NS) STORES((s + 1) & 1);
    }

    // epilogue: f = f0 + wni*32 + nt*8 + 2*l3 (+1); gate = c[mt][nt], up = c[mt][nt+4]
    int gbase = g_off[e];
#pragma unroll
    for (int mt = 0; mt < 4; mt++)
#pragma unroll
        for (int rr = 0; rr < 2; rr++) {
            int row = wmi * 64 + mt * 16 + lr + rr * 8;
            if (m0 + row < cnt) {
                float w = swt[row];
                float* dst = g_act + (size_t)(gbase + m0 + row) * FDIM + f0 + wni * 32 + 2 * l3;
#pragma unroll
                for (int nt = 0; nt < 4; nt++) {
                    float gv0 = c[mt][nt][rr * 2],     gv1 = c[mt][nt][rr * 2 + 1];
                    float uv0 = c[mt][nt + 4][rr * 2], uv1 = c[mt][nt + 4][rr * 2 + 1];
                    float2 o;
                    o.x = w * (gv0 / (1.0f + expf(-gv0))) * uv0;
                    o.y = w * (gv1 / (1.0f + expf(-gv1))) * uv1;
                    *(float2*)(dst + nt * 8) = o;
                }
            }
        }
}

// =====================================================================
// down GEMM. Block 128m x 256n (H cols), BK=16, 256 threads, warp 64x64.
// =====================================================================
__global__ __launch_bounds__(256, 1) void mg_down(const float* __restrict__ Wd)
{
    extern __shared__ uint32_t sm[];
    int e = blockIdx.z;
    int cnt = g_cnt[e];
    int m0 = blockIdx.x * 128;
    if (m0 >= cnt) return;
    int h0 = blockIdx.y * 256;

    int tid = threadIdx.x, lane = tid & 31, wid = tid >> 5;
    int wmi = wid >> 2, wni = wid & 3;
    int lr = lane >> 2, l3 = lane & 3;
    int gbase = g_off[e];

    int am = tid >> 1, kb8 = (tid & 1) * 8;
    const float* arow = g_act + (size_t)(gbase + min(m0 + am, cnt - 1)) * FDIM + kb8;
    int fq = lane * 4, kq = wid;
    const float* dB = Wd + (size_t)e * FDIM * HDIM + (size_t)kq * HDIM + h0 + fq;
    uint32_t bswz = 4 * (kq & 1);

    float4 ra0, ra1, v0, v1, v2, v3;
    auto LOADG = [&](int s) {
        int kb = s * 16;
        ra0 = *(const float4*)(arow + kb);
        ra1 = *(const float4*)(arow + kb + 4);
        v0 = *(const float4*)(dB + (size_t)kb * HDIM);
        v1 = *(const float4*)(dB + (size_t)(kb + 8) * HDIM);
        v2 = *(const float4*)(dB + (size_t)kb * HDIM + 128);
        v3 = *(const float4*)(dB + (size_t)(kb + 8) * HDIM + 128);
    };
    auto STORES = [&](int b) {
        uint32_t* A = sm + ABUF(b);
        uint32_t* B = sm + BBUF(b);
        const float* a0 = (const float*)&ra0;
        const float* a1 = (const float*)&ra1;
#pragma unroll
        for (int j = 0; j < 4; j++) {
            A[(kb8 + j) * AST + am]     = tf32r(a0[j]);
            A[(kb8 + 4 + j) * AST + am] = tf32r(a1[j]);
        }
        uint32_t cg = fq ^ bswz;
        uint4 t0 = { tf32r(v0.x), tf32r(v0.y), tf32r(v0.z), tf32r(v0.w) };
        uint4 t1 = { tf32r(v1.x), tf32r(v1.y), tf32r(v1.z), tf32r(v1.w) };
        uint4 t2 = { tf32r(v2.x), tf32r(v2.y), tf32r(v2.z), tf32r(v2.w) };
        uint4 t3 = { tf32r(v3.x), tf32r(v3.y), tf32r(v3.z), tf32r(v3.w) };
        *(uint4*)(B + kq * BST + cg)             = t0;
        *(uint4*)(B + (kq + 8) * BST + cg)       = t1;
        *(uint4*)(B + kq * BST + 128 + cg)       = t2;
        *(uint4*)(B + (kq + 8) * BST + 128 + cg) = t3;
    };

    float c[4][8][4];
#pragma unroll
    for (int a = 0; a < 4; a++)
#pragma unroll
        for (int b = 0; b < 8; b++)
#pragma unroll
            for (int k = 0; k < 4; k++) c[a][b][k] = 0.0f;

    int fswz = 4 * (l3 & 1);
    uint32_t aoff = l3 * AST + wmi * 64 + lr;
    uint32_t boff = l3 * BST + ((wni * 64 + lr) ^ fswz);

    LOADG(0); STORES(0);
    const int NS = FDIM / 16;
    for (int s = 0; s < NS; s++) {
        __syncthreads();
        if (s + 1 < NS) LOADG(s + 1);
        uint32_t* A = sm + ABUF(s & 1);
        uint32_t* B = sm + BBUF(s & 1);
#pragma unroll
        for (int kk = 0; kk < 16; kk += 8) {
            uint32_t af[4][4];
#pragma unroll
            for (int mt = 0; mt < 4; mt++) {
                uint32_t w = aoff + kk * AST + mt * 16;
                af[mt][0] = A[w];
                af[mt][1] = A[w + 8];
                af[mt][2] = A[w + 4 * AST];
                af[mt][3] = A[w + 4 * AST + 8];
            }
#pragma unroll
            for (int nt = 0; nt < 8; nt++) {
                uint32_t w = boff + kk * BST + nt * 8;
                uint32_t b0 = B[w], b1 = B[w + 4 * BST];
#pragma unroll
                for (int mt = 0; mt < 4; mt++)
                    MMA(c[mt][nt], af[mt][0], af[mt][1], af[mt][2], af[mt][3], b0, b1);
            }
        }
        if (s + 1 < NS) STORES((s + 1) & 1);
    }

#pragma unroll
    for (int mt = 0; mt < 4; mt++)
#pragma unroll
        for (int rr = 0; rr < 2; rr++) {
            int row = wmi * 64 + mt * 16 + lr + rr * 8;
            if (m0 + row < cnt) {
                float* dst = g_dout + (size_t)(gbase + m0 + row) * HDIM + h0 + wni * 64 + 2 * l3;
#pragma unroll
                for (int nt = 0; nt < 8; nt++)
                    *(float2*)(dst + nt * 8) =
                        make_float2(c[mt][nt][rr * 2], c[mt][nt][rr * 2 + 1]);
            }
        }
}

// ---------------- combine ----------------
__global__ __launch_bounds__(256) void combine_kernel(float* __restrict__ out)
{
    int idx = blockIdx.x * blockDim.x + threadIdx.x;
    int t = idx >> 8;
    int hq = (idx & 255) * 4;
    int v0 = g_pair[t * 2 + 0], v1 = g_pair[t * 2 + 1];
    int gi0 = g_off[v0 >> 12] + (v0 & (MAXP - 1));
    int gi1 = g_off[v1 >> 12] + (v1 & (MAXP - 1));
    float4 a = *(const float4*)(g_dout + (size_t)gi0 * HDIM + hq);
    float4 b = *(const float4*)(g_dout + (size_t)gi1 * HDIM + hq);
    float4 o = {a.x + b.x, a.y + b.y, a.z + b.z, a.w + b.w};
    *(float4*)(out + (size_t)t * HDIM + hq) = o;
}

// ---------------- launch ----------------
extern "C" void kernel_launch(void* const* d_in, const int* in_sizes, int n_in,
                              void* d_out, int out_size)
{
    const float* x  = (const float*)d_in[0];
    const float* Wr = (const float*)d_in[1];
    const float* Wg = (const float*)d_in[2];
    const float* Wu = (const float*)d_in[3];
    const float* Wd = (const float*)d_in[4];
    float* out = (float*)d_out;

    cudaFuncSetAttribute(mg_gateup, cudaFuncAttributeMaxDynamicSharedMemorySize, GEMM_SMEM);
    cudaFuncSetAttribute(mg_down,   cudaFuncAttributeMaxDynamicSharedMemorySize, GEMM_SMEM);

    zero_cnt_kernel<<<1, 32>>>();
    router_kernel<<<T_TOK / 4, 128>>>(x, Wr);
    scan_kernel<<<1, 32>>>();

    dim3 gg(MAXP / 128, FDIM / 128, NEXP);   // early-exit on m
    mg_gateup<<<gg, 256, GEMM_SMEM>>>(x, Wg, Wu);

    dim3 gd(MAXP / 128, HDIM / 256, NEXP);
    mg_down<<<gd, 256, GEMM_SMEM>>>(Wd);

    combine_kernel<<<(T_TOK * HDIM / 4) / 256, 256>>>(out);
}

// round 7
// speedup vs baseline: 3.8769x; 1.5183x over previous
#include <cuda_runtime.h>
#include <cuda_fp16.h>
#include <math.h>
#include <stdint.h>

#define T_TOK 4096
#define HDIM 1024
#define FDIM 512
#define NEXP 8
#define MAXP 4096
#define MAXTILE 96

// ---------------- device scratch ----------------
__device__ int    g_cnt[NEXP];
__device__ int    g_off[NEXP];
__device__ int    g_tok[NEXP * MAXP];
__device__ float  g_wt [NEXP * MAXP];
__device__ int    g_pair[T_TOK * 2];
__device__ int    g_tbl[MAXTILE];
__device__ int    g_ntile;
__device__ __half g_xh  [T_TOK * HDIM];          // fp16 copy of x
__device__ __half g_acth[T_TOK * 2 * FDIM];      // fp16 SwiGLU activations
__device__ float  g_dout[T_TOK * 2 * HDIM];

#define MMA16(c, a0, a1, a2, a3, b0, b1) \
    asm volatile("mma.sync.aligned.m16n8k16.row.col.f32.f16.f16.f32 " \
        "{%0,%1,%2,%3},{%4,%5,%6,%7},{%8,%9},{%0,%1,%2,%3};" \
        : "+f"((c)[0]), "+f"((c)[1]), "+f"((c)[2]), "+f"((c)[3]) \
        : "r"(a0), "r"(a1), "r"(a2), "r"(a3), "r"(b0), "r"(b1))

__device__ __forceinline__ uint32_t h2u(__half2 h) {
    uint32_t u; asm("mov.b32 %0, %1;" : "=r"(u) : "r"(*(uint32_t*)&h)); return u;
}

// smem (uint2 units): A 8q x 132m, B 8q x 132n, per buffer 2112 uint2
#define QST 132
#define BUF2 2112
#define AOFF(b) ((b) * BUF2)
#define BOFF(b) ((b) * BUF2 + 8 * QST)
#define META2 (2 * BUF2)
#define GEMM_SMEM (2 * BUF2 * 8 + 1024)

// ---------------- tiny setup ----------------
__global__ void zero_cnt_kernel() { if (threadIdx.x < NEXP) g_cnt[threadIdx.x] = 0; }
__global__ void scan_kernel() {
    if (threadIdx.x == 0) {
        int o = 0, nt = 0;
        for (int e = 0; e < NEXP; e++) {
            g_off[e] = o;
            int c = g_cnt[e];
            for (int m0 = 0; m0 < c; m0 += 128) g_tbl[nt++] = (e << 12) | m0;
            o += c;
        }
        g_ntile = nt;
    }
}

// ---------------- router (fp32-exact) + x->fp16 ----------------
__global__ __launch_bounds__(128) void router_kernel(
    const float* __restrict__ x, const float* __restrict__ Wr)
{
    int t = blockIdx.x * 4 + (threadIdx.x >> 5);
    int lane = threadIdx.x & 31;
    const float* xr = x + (size_t)t * HDIM;
    float acc[NEXP];
#pragma unroll
    for (int e = 0; e < NEXP; e++) acc[e] = 0.0f;
    for (int h = lane; h < HDIM; h += 32) {
        float xv = xr[h];
        g_xh[(size_t)t * HDIM + h] = __float2half_rn(xv);
        const float4* wr4 = (const float4*)(Wr + (size_t)h * NEXP);
        float4 w0 = wr4[0], w1 = wr4[1];
        acc[0] = fmaf(xv, w0.x, acc[0]); acc[1] = fmaf(xv, w0.y, acc[1]);
        acc[2] = fmaf(xv, w0.z, acc[2]); acc[3] = fmaf(xv, w0.w, acc[3]);
        acc[4] = fmaf(xv, w1.x, acc[4]); acc[5] = fmaf(xv, w1.y, acc[5]);
        acc[6] = fmaf(xv, w1.z, acc[6]); acc[7] = fmaf(xv, w1.w, acc[7]);
    }
#pragma unroll
    for (int e = 0; e < NEXP; e++)
#pragma unroll
        for (int o = 16; o > 0; o >>= 1)
            acc[e] += __shfl_xor_sync(0xFFFFFFFFu, acc[e], o);
    if (lane == 0) {
        float m = acc[0];
#pragma unroll
        for (int e = 1; e < NEXP; e++) m = fmaxf(m, acc[e]);
        float p[NEXP];
#pragma unroll
        for (int e = 0; e < NEXP; e++) p[e] = expf(acc[e] - m);
        int i0 = 0;
#pragma unroll
        for (int e = 1; e < NEXP; e++) if (p[e] > p[i0]) i0 = e;
        int i1 = (i0 == 0) ? 1 : 0;
#pragma unroll
        for (int e = 0; e < NEXP; e++) if (e != i0 && p[e] > p[i1]) i1 = e;
        float s = p[i0] + p[i1];
        int p0 = atomicAdd(&g_cnt[i0], 1);
        g_tok[i0 * MAXP + p0] = t; g_wt[i0 * MAXP + p0] = p[i0] / s;
        g_pair[t * 2 + 0] = i0 * MAXP + p0;
        int p1 = atomicAdd(&g_cnt[i1], 1);
        g_tok[i1 * MAXP + p1] = t; g_wt[i1 * MAXP + p1] = p[i1] / s;
        g_pair[t * 2 + 1] = i1 * MAXP + p1;
    }
}

// =====================================================================
// gate+up fp16 GEMM + SwiGLU. Block 128m x 128n' (n' 16-interleaved
// gate/up), BK=32, 256 threads, 8 warps (2m x 4n), warp tile 64x32.
// =====================================================================
__global__ __launch_bounds__(256, 2) void mg_gateup(
    const float* __restrict__ Wg,
    const float* __restrict__ Wu)
{
    extern __shared__ uint2 sm2[];
    int tile = blockIdx.x;
    if (tile >= g_ntile) return;
    int pk = g_tbl[tile];
    int e = pk >> 12, m0 = pk & 4095;
    int cnt = g_cnt[e];
    int f0 = blockIdx.y * 64;

    int tid = threadIdx.x, lane = tid & 31, wid = tid >> 5;
    int wmi = wid >> 2, wni = wid & 3;
    int lr = lane >> 2, l3 = lane & 3;

    int*   stok = (int*)(sm2 + META2);
    float* swt  = (float*)(sm2 + META2 + 64);
    if (tid < 128) {
        int r = m0 + tid, rc = min(r, cnt - 1);
        stok[tid] = g_tok[e * MAXP + rc];
        swt[tid]  = (r < cnt) ? g_wt[e * MAXP + rc] : 0.0f;
    }
    __syncthreads();

    // A staging: m = tid>>1, kh = (tid&1)*16; source fp16 rows of g_xh
    int am = tid >> 1, kh = (tid & 1) * 16;
    const __half* arow = g_xh + (size_t)stok[am] * HDIM + kh;
    int aqb = (tid & 1) * 4;
    // B staging: rows {2p,2p+1,2p+8,2p+9}, p = (wid&3)+8*(wid>>2) -> q = wid
    int bp = (wid & 3) + 8 * (wid >> 2);
    int n4 = lane * 4;
    int bmat = (n4 >> 4) & 1;
    int bf = ((n4 >> 5) << 4) + (((n4 >> 3) & 1) << 3) + (n4 & 7);
    const float* wsel = (bmat ? Wu : Wg) + (size_t)e * HDIM * FDIM + f0 + bf;

    uint4 au0, au1;
    float4 bv0, bv1, bv2, bv3;
    auto LOADG = [&](int s) {
        int kb = s * 32;
        const uint4* ap = (const uint4*)(arow + kb);
        au0 = ap[0]; au1 = ap[1];
        const float* bp0 = wsel + (size_t)(kb + 2 * bp) * FDIM;
        bv0 = *(const float4*)bp0;
        bv1 = *(const float4*)(bp0 + FDIM);
        bv2 = *(const float4*)(bp0 + 8 * FDIM);
        bv3 = *(const float4*)(bp0 + 9 * FDIM);
    };
    auto STORES = [&](int b) {
        uint2* A = sm2 + AOFF(b);
        uint2* B = sm2 + BOFF(b);
        const uint32_t* a0 = (const uint32_t*)&au0;
        const uint32_t* a1 = (const uint32_t*)&au1;
#pragma unroll
        for (int j = 0; j < 4; j++)
            A[(aqb + j) * QST + am] = make_uint2(a0[j], a1[j]);
        const float* v0 = (const float*)&bv0;
        const float* v1 = (const float*)&bv1;
        const float* v2 = (const float*)&bv2;
        const float* v3 = (const float*)&bv3;
#pragma unroll
        for (int j = 0; j < 4; j++) {
            uint32_t lo = h2u(__floats2half2_rn(v0[j], v1[j]));
            uint32_t hi = h2u(__floats2half2_rn(v2[j], v3[j]));
            B[wid * QST + n4 + j] = make_uint2(lo, hi);
        }
    };

    float c[4][4][4];
#pragma unroll
    for (int a = 0; a < 4; a++)
#pragma unroll
        for (int b = 0; b < 4; b++)
#pragma unroll
            for (int k = 0; k < 4; k++) c[a][b][k] = 0.0f;

    LOADG(0); STORES(0);
    const int NS = HDIM / 32;
    for (int s = 0; s < NS; s++) {
        __syncthreads();
        if (s + 1 < NS) LOADG(s + 1);
        uint2* A = sm2 + AOFF(s & 1);
        uint2* B = sm2 + BOFF(s & 1);
#pragma unroll
        for (int kk = 0; kk < 2; kk++) {
            int q = kk * 4 + l3;
            uint2 af[4], ah[4];
#pragma unroll
            for (int mt = 0; mt < 4; mt++) {
                int m = wmi * 64 + mt * 16 + lr;
                af[mt] = A[q * QST + m];
                ah[mt] = A[q * QST + m + 8];
            }
#pragma unroll
            for (int nt = 0; nt < 4; nt++) {
                uint2 b = B[q * QST + wni * 32 + nt * 8 + lr];
#pragma unroll
                for (int mt = 0; mt < 4; mt++)
                    MMA16(c[mt][nt], af[mt].x, ah[mt].x, af[mt].y, ah[mt].y, b.x, b.y);
            }
        }
        if (s + 1 < NS) STORES((s + 1) & 1);
    }

    // epilogue: nt 0,1 gate / nt 2,3 up at f = f0 + wni*16 + (nt&1)*8 + 2*l3
    int gbase = g_off[e];
#pragma unroll
    for (int mt = 0; mt < 4; mt++)
#pragma unroll
        for (int rr = 0; rr < 2; rr++) {
            int row = wmi * 64 + mt * 16 + lr + rr * 8;
            if (m0 + row < cnt) {
                float w = swt[row];
                __half* dst = g_acth + (size_t)(gbase + m0 + row) * FDIM + f0 + wni * 16 + 2 * l3;
#pragma unroll
                for (int ntl = 0; ntl < 2; ntl++) {
                    float gv0 = c[mt][ntl][rr * 2],     gv1 = c[mt][ntl][rr * 2 + 1];
                    float uv0 = c[mt][ntl + 2][rr * 2], uv1 = c[mt][ntl + 2][rr * 2 + 1];
                    float o0 = w * (gv0 / (1.0f + expf(-gv0))) * uv0;
                    float o1 = w * (gv1 / (1.0f + expf(-gv1))) * uv1;
                    *(__half2*)(dst + ntl * 8) = __floats2half2_rn(o0, o1);
                }
            }
        }
}

// =====================================================================
// down fp16 GEMM. Block 128m x 128h, BK=32, 256 threads, warp 64x32.
// =====================================================================
__global__ __launch_bounds__(256, 2) void mg_down(const float* __restrict__ Wd)
{
    extern __shared__ uint2 sm2[];
    int tile = blockIdx.x;
    if (tile >= g_ntile) return;
    int pk = g_tbl[tile];
    int e = pk >> 12, m0 = pk & 4095;
    int cnt = g_cnt[e];
    int h0 = blockIdx.y * 128;

    int tid = threadIdx.x, lane = tid & 31, wid = tid >> 5;
    int wmi = wid >> 2, wni = wid & 3;
    int lr = lane >> 2, l3 = lane & 3;
    int gbase = g_off[e];

    int am = tid >> 1, kh = (tid & 1) * 16;
    const __half* arow = g_acth + (size_t)(gbase + min(m0 + am, cnt - 1)) * FDIM + kh;
    int aqb = (tid & 1) * 4;
    int bp = (wid & 3) + 8 * (wid >> 2);
    int n4 = lane * 4;
    const float* wsel = Wd + (size_t)e * FDIM * HDIM + h0 + n4;

    uint4 au0, au1;
    float4 bv0, bv1, bv2, bv3;
    auto LOADG = [&](int s) {
        int kb = s * 32;
        const uint4* ap = (const uint4*)(arow + kb);
        au0 = ap[0]; au1 = ap[1];
        const float* bp0 = wsel + (size_t)(kb + 2 * bp) * HDIM;
        bv0 = *(const float4*)bp0;
        bv1 = *(const float4*)(bp0 + HDIM);
        bv2 = *(const float4*)(bp0 + 8 * HDIM);
        bv3 = *(const float4*)(bp0 + 9 * HDIM);
    };
    auto STORES = [&](int b) {
        uint2* A = sm2 + AOFF(b);
        uint2* B = sm2 + BOFF(b);
        const uint32_t* a0 = (const uint32_t*)&au0;
        const uint32_t* a1 = (const uint32_t*)&au1;
#pragma unroll
        for (int j = 0; j < 4; j++)
            A[(aqb + j) * QST + am] = make_uint2(a0[j], a1[j]);
        const float* v0 = (const float*)&bv0;
        const float* v1 = (const float*)&bv1;
        const float* v2 = (const float*)&bv2;
        const float* v3 = (const float*)&bv3;
#pragma unroll
        for (int j = 0; j < 4; j++) {
            uint32_t lo = h2u(__floats2half2_rn(v0[j], v1[j]));
            uint32_t hi = h2u(__floats2half2_rn(v2[j], v3[j]));
            B[wid * QST + n4 + j] = make_uint2(lo, hi);
        }
    };

    float c[4][4][4];
#pragma unroll
    for (int a = 0; a < 4; a++)
#pragma unroll
        for (int b = 0; b < 4; b++)
#pragma unroll
            for (int k = 0; k < 4; k++) c[a][b][k] = 0.0f;

    LOADG(0); STORES(0);
    const int NS = FDIM / 32;
    for (int s = 0; s < NS; s++) {
        __syncthreads();
        if (s + 1 < NS) LOADG(s + 1);
        uint2* A = sm2 + AOFF(s & 1);
        uint2* B = sm2 + BOFF(s & 1);
#pragma unroll
        for (int kk = 0; kk < 2; kk++) {
            int q = kk * 4 + l3;
            uint2 af[4], ah[4];
#pragma unroll
            for (int mt = 0; mt < 4; mt++) {
                int m = wmi * 64 + mt * 16 + lr;
                af[mt] = A[q * QST + m];
                ah[mt] = A[q * QST + m + 8];
            }
#pragma unroll
            for (int nt = 0; nt < 4; nt++) {
                uint2 b = B[q * QST + wni * 32 + nt * 8 + lr];
#pragma unroll
                for (int mt = 0; mt < 4; mt++)
                    MMA16(c[mt][nt], af[mt].x, ah[mt].x, af[mt].y, ah[mt].y, b.x, b.y);
            }
        }
        if (s + 1 < NS) STORES((s + 1) & 1);
    }

#pragma unroll
    for (int mt = 0; mt < 4; mt++)
#pragma unroll
        for (int rr = 0; rr < 2; rr++) {
            int row = wmi * 64 + mt * 16 + lr + rr * 8;
            if (m0 + row < cnt) {
                float* dst = g_dout + (size_t)(gbase + m0 + row) * HDIM + h0 + wni * 32 + 2 * l3;
#pragma unroll
                for (int nt = 0; nt < 4; nt++)
                    *(float2*)(dst + nt * 8) =
                        make_float2(c[mt][nt][rr * 2], c[mt][nt][rr * 2 + 1]);
            }
        }
}

// ---------------- combine ----------------
__global__ __launch_bounds__(256) void combine_kernel(float* __restrict__ out)
{
    int idx = blockIdx.x * blockDim.x + threadIdx.x;
    int t = idx >> 8;
    int hq = (idx & 255) * 4;
    int v0 = g_pair[t * 2 + 0], v1 = g_pair[t * 2 + 1];
    int gi0 = g_off[v0 >> 12] + (v0 & (MAXP - 1));
    int gi1 = g_off[v1 >> 12] + (v1 & (MAXP - 1));
    float4 a = *(const float4*)(g_dout + (size_t)gi0 * HDIM + hq);
    float4 b = *(const float4*)(g_dout + (size_t)gi1 * HDIM + hq);
    float4 o = {a.x + b.x, a.y + b.y, a.z + b.z, a.w + b.w};
    *(float4*)(out + (size_t)t * HDIM + hq) = o;
}

// ---------------- launch ----------------
extern "C" void kernel_launch(void* const* d_in, const int* in_sizes, int n_in,
                              void* d_out, int out_size)
{
    const float* x  = (const float*)d_in[0];
    const float* Wr = (const float*)d_in[1];
    const float* Wg = (const float*)d_in[2];
    const float* Wu = (const float*)d_in[3];
    const float* Wd = (const float*)d_in[4];
    float* out = (float*)d_out;

    cudaFuncSetAttribute(mg_gateup, cudaFuncAttributeMaxDynamicSharedMemorySize, GEMM_SMEM);
    cudaFuncSetAttribute(mg_down,   cudaFuncAttributeMaxDynamicSharedMemorySize, GEMM_SMEM);

    zero_cnt_kernel<<<1, 32>>>();
    router_kernel<<<T_TOK / 4, 128>>>(x, Wr);
    scan_kernel<<<1, 32>>>();

    dim3 gg(72, FDIM / 64);    // tile table x, f-block y
    mg_gateup<<<gg, 256, GEMM_SMEM>>>(Wg, Wu);

    dim3 gd(72, HDIM / 128);
    mg_down<<<gd, 256, GEMM_SMEM>>>(Wd);

    combine_kernel<<<(T_TOK * HDIM / 4) / 256, 256>>>(out);
}